// round 6
// baseline (speedup 1.0000x reference)
#include <cuda_runtime.h>

#define NMAX 100000
#define EPSV 1e-5f

// Scratch: hw[n][o] = sum_h relu(bn1(x@w1))[n][h] * conv_w[o][3+h]
__device__ __align__(256) float g_hw[NMAX * 64];

// ---------------------------------------------------------------------------
// Kernel A: per row n:  h = relu(bn1(x[n] @ w1));  hw[n] = h @ conv_w[:,3:]^T
// One warp per row; lane owns output channels (lane, lane+32).
// ---------------------------------------------------------------------------
__global__ __launch_bounds__(256) void edge_kernel_a(
    const float* __restrict__ x,
    const float* __restrict__ w1,
    const float* __restrict__ g1, const float* __restrict__ b1,
    const float* __restrict__ m1, const float* __restrict__ v1,
    const float* __restrict__ conv_w,
    int N)
{
    __shared__ float w1sm[64 * 64];   // w1[c][pp], addr c*64+pp
    __shared__ float w2sm[64 * 65];   // w2sm[h*65+o] = conv_w[o*67+3+h] (padded, conflict-free)
    __shared__ float s1sm[64], c1sm[64];
    __shared__ float buf[8][64];

    const int tid = threadIdx.x;
    for (int i = tid; i < 64 * 64; i += 256) w1sm[i] = w1[i];
    for (int i = tid; i < 64 * 64; i += 256) {
        int o = i >> 6, h = i & 63;                // consecutive tid -> consecutive h (coalesced gmem read)
        w2sm[h * 65 + o] = conv_w[o * 67 + 3 + h]; // padded stride avoids STS bank conflicts
    }
    if (tid < 64) {
        float s = g1[tid] * rsqrtf(v1[tid] + EPSV);
        s1sm[tid] = s;
        c1sm[tid] = b1[tid] - m1[tid] * s;
    }
    __syncthreads();

    const int lane = tid & 31;
    const int wrp  = tid >> 5;
    const int warpGlobal = blockIdx.x * 8 + wrp;
    const int nWarps     = gridDim.x * 8;
    float* xb = buf[wrp];

    for (int n = warpGlobal; n < N; n += nWarps) {
        float2 xv = reinterpret_cast<const float2*>(x + (size_t)n * 64)[lane];
        xb[2 * lane]     = xv.x;
        xb[2 * lane + 1] = xv.y;
        __syncwarp();

        float ha = 0.f, hb = 0.f;
        #pragma unroll
        for (int c = 0; c < 64; c++) {
            float xc = xb[c];
            ha = fmaf(xc, w1sm[c * 64 + lane],      ha);
            hb = fmaf(xc, w1sm[c * 64 + lane + 32], hb);
        }
        ha = fmaxf(fmaf(ha, s1sm[lane],      c1sm[lane]),      0.f);
        hb = fmaxf(fmaf(hb, s1sm[lane + 32], c1sm[lane + 32]), 0.f);

        __syncwarp();
        xb[lane]      = ha;
        xb[lane + 32] = hb;
        __syncwarp();

        float oa = 0.f, ob = 0.f;
        #pragma unroll
        for (int h = 0; h < 64; h++) {
            float hv = xb[h];
            oa = fmaf(hv, w2sm[h * 65 + lane],      oa);
            ob = fmaf(hv, w2sm[h * 65 + lane + 32], ob);
        }
        g_hw[(size_t)n * 64 + lane]      = oa;
        g_hw[(size_t)n * 64 + lane + 32] = ob;
        __syncwarp();   // all lanes done with xb before next iteration overwrites it
    }
}

// ---------------------------------------------------------------------------
// Kernel B: per point n:
//   f[o] = max_k relu( bn2( hw[idx[n,k]][o] + rel(n,k) . conv_w[o,0:3] ) )
//   out[n] = relu( bn3(f @ w3) + x[n] )
// One warp per point. Gather phase: lane owns channels (2l, 2l+1) -> one
// LDG.64 per lane = fully coalesced 256B row fetch of hw (L2-resident).
// Final GEMV: lane owns channels (l, l+32) via shared f buffer.
// ---------------------------------------------------------------------------
__global__ __launch_bounds__(256) void edge_kernel_b(
    const float* __restrict__ p, const float* __restrict__ x,
    const int*   __restrict__ idx,
    const float* __restrict__ conv_w,
    const float* __restrict__ g2, const float* __restrict__ b2,
    const float* __restrict__ m2, const float* __restrict__ v2,
    const float* __restrict__ w3,
    const float* __restrict__ g3, const float* __restrict__ b3,
    const float* __restrict__ m3, const float* __restrict__ v3,
    float* __restrict__ out, int N)
{
    __shared__ float w3sm[64 * 64];   // w3[o][c], addr o*64+c
    __shared__ float fbuf[8][64];

    const int tid = threadIdx.x;
    for (int i = tid; i < 64 * 64; i += 256) w3sm[i] = w3[i];

    const int lane = tid & 31;
    const int wrp  = tid >> 5;

    // Per-lane folded constants
    const int c0 = 2 * lane, c1 = 2 * lane + 1;
    float s2a = g2[c0] * rsqrtf(v2[c0] + EPSV);
    float k2a = b2[c0] - m2[c0] * s2a;
    float s2b = g2[c1] * rsqrtf(v2[c1] + EPSV);
    float k2b = b2[c1] - m2[c1] * s2b;
    float wax = conv_w[c0 * 67 + 0], way = conv_w[c0 * 67 + 1], waz = conv_w[c0 * 67 + 2];
    float wbx = conv_w[c1 * 67 + 0], wby = conv_w[c1 * 67 + 1], wbz = conv_w[c1 * 67 + 2];
    float s3a = g3[lane]      * rsqrtf(v3[lane]      + EPSV);
    float k3a = b3[lane]      - m3[lane]      * s3a;
    float s3b = g3[lane + 32] * rsqrtf(v3[lane + 32] + EPSV);
    float k3b = b3[lane + 32] - m3[lane + 32] * s3b;
    __syncthreads();

    const int warpGlobal = blockIdx.x * 8 + wrp;
    const int nWarps     = gridDim.x * 8;
    float* fb = fbuf[wrp];

    for (int n = warpGlobal; n < N; n += nWarps) {
        int jreg = (lane < 16) ? idx[(size_t)n * 16 + lane] : 0;
        float px = p[n * 3 + 0], py = p[n * 3 + 1], pz = p[n * 3 + 2];

        // ReLU folded into max by starting at 0
        float ma = 0.f, mb = 0.f;
        #pragma unroll
        for (int k = 0; k < 16; k++) {
            int j = __shfl_sync(0xffffffffu, jreg, k);
            float qx = p[j * 3 + 0] - px;
            float qy = p[j * 3 + 1] - py;
            float qz = p[j * 3 + 2] - pz;
            float2 hw = reinterpret_cast<const float2*>(g_hw + (size_t)j * 64)[lane];
            float e0 = fmaf(qx, wax, fmaf(qy, way, fmaf(qz, waz, hw.x)));
            float e1 = fmaf(qx, wbx, fmaf(qy, wby, fmaf(qz, wbz, hw.y)));
            ma = fmaxf(ma, fmaf(e0, s2a, k2a));
            mb = fmaxf(mb, fmaf(e1, s2b, k2b));
        }

        __syncwarp();
        fb[c0] = ma;
        fb[c1] = mb;
        __syncwarp();

        float oa = 0.f, ob = 0.f;
        #pragma unroll
        for (int o = 0; o < 64; o++) {
            float fv = fb[o];                 // warp-broadcast read
            oa = fmaf(fv, w3sm[o * 64 + lane],      oa);
            ob = fmaf(fv, w3sm[o * 64 + lane + 32], ob);
        }
        float xa = x[(size_t)n * 64 + lane];
        float xc = x[(size_t)n * 64 + lane + 32];
        oa = fmaf(oa, s3a, k3a) + xa;
        ob = fmaf(ob, s3b, k3b) + xc;
        out[(size_t)n * 64 + lane]      = fmaxf(oa, 0.f);
        out[(size_t)n * 64 + lane + 32] = fmaxf(ob, 0.f);
    }
}

extern "C" void kernel_launch(void* const* d_in, const int* in_sizes, int n_in,
                              void* d_out, int out_size)
{
    const float* p      = (const float*)d_in[0];
    const float* x      = (const float*)d_in[1];
    const int*   idx    = (const int*)  d_in[2];
    const float* w1     = (const float*)d_in[3];
    const float* g1     = (const float*)d_in[4];
    const float* b1     = (const float*)d_in[5];
    const float* m1     = (const float*)d_in[6];
    const float* v1     = (const float*)d_in[7];
    const float* conv_w = (const float*)d_in[8];
    const float* g2     = (const float*)d_in[9];
    const float* b2     = (const float*)d_in[10];
    const float* m2     = (const float*)d_in[11];
    const float* v2     = (const float*)d_in[12];
    const float* w3     = (const float*)d_in[13];
    const float* g3     = (const float*)d_in[14];
    const float* b3     = (const float*)d_in[15];
    const float* m3     = (const float*)d_in[16];
    const float* v3     = (const float*)d_in[17];
    float* out = (float*)d_out;

    int N = in_sizes[0] / 3;
    if (N > NMAX) N = NMAX;

    edge_kernel_a<<<888, 256>>>(x, w1, g1, b1, m1, v1, conv_w, N);
    edge_kernel_b<<<1184, 256>>>(p, x, idx, conv_w,
                                 g2, b2, m2, v2,
                                 w3, g3, b3, m3, v3,
                                 out, N);
}

// round 7
// speedup vs baseline: 1.8539x; 1.8539x over previous
#include <cuda_runtime.h>

#define NMAX 100000
#define EPSV 1e-5f

// Scratch: hq[n][o] = hw[n][o] + p[n]._dot(conv_w[o,0:3])
//   where hw[n][o] = sum_h relu(bn1(x@w1))[n][h] * conv_w[o][3+h]
__device__ __align__(256) float g_hq[NMAX * 64];

// ---------------------------------------------------------------------------
// Kernel A: 4 rows per warp.
//   h = relu(bn1(x[n] @ w1));  hq[n] = h @ conv_w[:,3:]^T + p[n]·conv_w[:,0:3]
// Lane owns output channels (lane, lane+32). Register-blocked GEMVs:
// per 4-channel block: 8 weight LDS + 4 LDS.128 broadcasts for 32 FMAs.
// ---------------------------------------------------------------------------
__global__ __launch_bounds__(256) void edge_kernel_a(
    const float* __restrict__ p,
    const float* __restrict__ x,
    const float* __restrict__ w1,
    const float* __restrict__ g1, const float* __restrict__ b1,
    const float* __restrict__ m1, const float* __restrict__ v1,
    const float* __restrict__ conv_w,
    int N)
{
    __shared__ float w1sm[64 * 64];             // w1[c][pp] at c*64+pp
    __shared__ float w2sm[64 * 65];             // w2sm[h*65+o] = conv_w[o*67+3+h]
    __shared__ float s1sm[64], c1sm[64];
    __shared__ __align__(16) float xbuf[8][4][64];

    const int tid = threadIdx.x;
    for (int i = tid; i < 64 * 64; i += 256) w1sm[i] = w1[i];
    for (int i = tid; i < 64 * 64; i += 256) {
        int o = i >> 6, h = i & 63;             // consecutive tid -> consecutive h (coalesced)
        w2sm[h * 65 + o] = conv_w[o * 67 + 3 + h];
    }
    if (tid < 64) {
        float s = g1[tid] * rsqrtf(v1[tid] + EPSV);
        s1sm[tid] = s;
        c1sm[tid] = b1[tid] - m1[tid] * s;
    }
    __syncthreads();

    const int lane = tid & 31;
    const int wrp  = tid >> 5;

    // per-lane xyz weights for output channels (lane, lane+32)
    const float wxa = conv_w[lane * 67 + 0];
    const float wya = conv_w[lane * 67 + 1];
    const float wza = conv_w[lane * 67 + 2];
    const float wxb = conv_w[(lane + 32) * 67 + 0];
    const float wyb = conv_w[(lane + 32) * 67 + 1];
    const float wzb = conv_w[(lane + 32) * 67 + 2];
    const float s1a = s1sm[lane],      c1a = c1sm[lane];
    const float s1b = s1sm[lane + 32], c1b = c1sm[lane + 32];

    const int group   = blockIdx.x * 8 + wrp;
    const int nGroups = gridDim.x * 8;
    float (*X)[64] = xbuf[wrp];

    for (int n0 = group * 4; n0 < N; n0 += nGroups * 4) {
        int   nr[4];
        float px[4], py[4], pz[4];
        #pragma unroll
        for (int r = 0; r < 4; r++) {
            int n = n0 + r; if (n >= N) n = N - 1;
            nr[r] = n;
            float2 xv = reinterpret_cast<const float2*>(x + (size_t)n * 64)[lane];
            X[r][2 * lane]     = xv.x;
            X[r][2 * lane + 1] = xv.y;
            px[r] = p[n * 3 + 0]; py[r] = p[n * 3 + 1]; pz[r] = p[n * 3 + 2];
        }
        __syncwarp();

        // ---- GEMV 1: h = x @ w1 ----
        float ha[4] = {0.f, 0.f, 0.f, 0.f};
        float hb[4] = {0.f, 0.f, 0.f, 0.f};
        #pragma unroll
        for (int c4 = 0; c4 < 64; c4 += 4) {
            float4 xq[4];
            #pragma unroll
            for (int r = 0; r < 4; r++)
                xq[r] = *reinterpret_cast<const float4*>(&X[r][c4]);
            #pragma unroll
            for (int j = 0; j < 4; j++) {
                float wA = w1sm[(c4 + j) * 64 + lane];
                float wB = w1sm[(c4 + j) * 64 + 32 + lane];
                #pragma unroll
                for (int r = 0; r < 4; r++) {
                    float xv = (&xq[r].x)[j];
                    ha[r] = fmaf(xv, wA, ha[r]);
                    hb[r] = fmaf(xv, wB, hb[r]);
                }
            }
        }
        // bn1 + relu, write h back to the row buffer
        __syncwarp();
        #pragma unroll
        for (int r = 0; r < 4; r++) {
            X[r][lane]      = fmaxf(fmaf(ha[r], s1a, c1a), 0.f);
            X[r][lane + 32] = fmaxf(fmaf(hb[r], s1b, c1b), 0.f);
        }
        __syncwarp();

        // ---- GEMV 2: hw = h @ conv_w[:,3:]^T ----
        float oa[4] = {0.f, 0.f, 0.f, 0.f};
        float ob[4] = {0.f, 0.f, 0.f, 0.f};
        #pragma unroll
        for (int c4 = 0; c4 < 64; c4 += 4) {
            float4 hq[4];
            #pragma unroll
            for (int r = 0; r < 4; r++)
                hq[r] = *reinterpret_cast<const float4*>(&X[r][c4]);
            #pragma unroll
            for (int j = 0; j < 4; j++) {
                float wA = w2sm[(c4 + j) * 65 + lane];
                float wB = w2sm[(c4 + j) * 65 + 32 + lane];
                #pragma unroll
                for (int r = 0; r < 4; r++) {
                    float hv = (&hq[r].x)[j];
                    oa[r] = fmaf(hv, wA, oa[r]);
                    ob[r] = fmaf(hv, wB, ob[r]);
                }
            }
        }

        // add p·w_xyz and store hq
        #pragma unroll
        for (int r = 0; r < 4; r++) {
            if (n0 + r < N) {
                float qa = fmaf(px[r], wxa, fmaf(py[r], wya, fmaf(pz[r], wza, oa[r])));
                float qb = fmaf(px[r], wxb, fmaf(py[r], wyb, fmaf(pz[r], wzb, ob[r])));
                g_hq[(size_t)nr[r] * 64 + lane]      = qa;
                g_hq[(size_t)nr[r] * 64 + lane + 32] = qb;
            }
        }
        __syncwarp();   // buffer reuse next iteration
    }
}

// ---------------------------------------------------------------------------
// Kernel B: 4 points per warp.
//   f[o] = max_k relu( s2[o]*hq[idx[n,k]][o] + (k2[o] - (p[n]·w_o)*s2[o]) )
//   out[n] = relu( bn3(f @ w3) + x[n] )
// Gather: lane owns channels (2l,2l+1) -> one LDG.64 per lane per k.
// GEMV: lane owns channels (l,l+32); register-blocked with LDS.128 broadcasts.
// ---------------------------------------------------------------------------
__global__ __launch_bounds__(256) void edge_kernel_b(
    const float* __restrict__ p, const float* __restrict__ x,
    const int*   __restrict__ idx,
    const float* __restrict__ conv_w,
    const float* __restrict__ g2, const float* __restrict__ b2,
    const float* __restrict__ m2, const float* __restrict__ v2,
    const float* __restrict__ w3,
    const float* __restrict__ g3, const float* __restrict__ b3,
    const float* __restrict__ m3, const float* __restrict__ v3,
    float* __restrict__ out, int N)
{
    __shared__ float w3sm[64 * 64];             // w3[o][c] at o*64+c
    __shared__ __align__(16) float fbuf[8][4][64];

    const int tid = threadIdx.x;
    for (int i = tid; i < 64 * 64; i += 256) w3sm[i] = w3[i];

    const int lane = tid & 31;
    const int wrp  = tid >> 5;

    // gather-phase channels (2l, 2l+1)
    const int c0 = 2 * lane, c1 = 2 * lane + 1;
    const float s2a = g2[c0] * rsqrtf(v2[c0] + EPSV);
    const float k2a = b2[c0] - m2[c0] * s2a;
    const float s2b = g2[c1] * rsqrtf(v2[c1] + EPSV);
    const float k2b = b2[c1] - m2[c1] * s2b;
    const float wax = conv_w[c0 * 67 + 0], way = conv_w[c0 * 67 + 1], waz = conv_w[c0 * 67 + 2];
    const float wbx = conv_w[c1 * 67 + 0], wby = conv_w[c1 * 67 + 1], wbz = conv_w[c1 * 67 + 2];
    // gemv-phase channels (l, l+32)
    const float s3a = g3[lane]      * rsqrtf(v3[lane]      + EPSV);
    const float k3a = b3[lane]      - m3[lane]      * s3a;
    const float s3b = g3[lane + 32] * rsqrtf(v3[lane + 32] + EPSV);
    const float k3b = b3[lane + 32] - m3[lane + 32] * s3b;
    __syncthreads();

    const int group   = blockIdx.x * 8 + wrp;
    const int nGroups = gridDim.x * 8;
    float (*F)[64] = fbuf[wrp];
    const long long maxIdxAddr = (long long)N * 16 - 1;

    for (int n0 = group * 4; n0 < N; n0 += nGroups * 4) {
        // 64 neighbor indices (4 rows x 16) via 2 coalesced loads
        long long base = (long long)n0 * 16;
        long long a0 = base + lane;        if (a0 > maxIdxAddr) a0 = maxIdxAddr;
        long long a1 = base + 32 + lane;   if (a1 > maxIdxAddr) a1 = maxIdxAddr;
        int j0 = idx[a0];
        int j1 = idx[a1];

        // per-row folded BN2 bias: cX[r] = k2 - (p[n]·w)·s2
        float cA[4], cB[4];
        #pragma unroll
        for (int r = 0; r < 4; r++) {
            int n = n0 + r; if (n >= N) n = N - 1;
            float px = p[n * 3 + 0], py = p[n * 3 + 1], pz = p[n * 3 + 2];
            float pwa = fmaf(px, wax, fmaf(py, way, pz * waz));
            float pwb = fmaf(px, wbx, fmaf(py, wby, pz * wbz));
            cA[r] = fmaf(-pwa, s2a, k2a);
            cB[r] = fmaf(-pwb, s2b, k2b);
        }

        // gather + bn2 + relu-folded max
        float ma[4] = {0.f, 0.f, 0.f, 0.f};
        float mb[4] = {0.f, 0.f, 0.f, 0.f};
        #pragma unroll
        for (int r = 0; r < 4; r++) {
            #pragma unroll
            for (int k = 0; k < 16; k++) {
                const int e = r * 16 + k;
                int j = __shfl_sync(0xffffffffu, (e < 32) ? j0 : j1, e & 31);
                float2 hq = reinterpret_cast<const float2*>(g_hq + (size_t)j * 64)[lane];
                ma[r] = fmaxf(ma[r], fmaf(hq.x, s2a, cA[r]));
                mb[r] = fmaxf(mb[r], fmaf(hq.y, s2b, cB[r]));
            }
        }

        __syncwarp();
        #pragma unroll
        for (int r = 0; r < 4; r++) {
            float2 v = make_float2(ma[r], mb[r]);
            *reinterpret_cast<float2*>(&F[r][2 * lane]) = v;
        }
        __syncwarp();

        // ---- GEMV: out = f @ w3 ----
        float oa[4] = {0.f, 0.f, 0.f, 0.f};
        float ob[4] = {0.f, 0.f, 0.f, 0.f};
        #pragma unroll
        for (int o4 = 0; o4 < 64; o4 += 4) {
            float4 fq[4];
            #pragma unroll
            for (int r = 0; r < 4; r++)
                fq[r] = *reinterpret_cast<const float4*>(&F[r][o4]);
            #pragma unroll
            for (int j = 0; j < 4; j++) {
                float wA = w3sm[(o4 + j) * 64 + lane];
                float wB = w3sm[(o4 + j) * 64 + 32 + lane];
                #pragma unroll
                for (int r = 0; r < 4; r++) {
                    float fv = (&fq[r].x)[j];
                    oa[r] = fmaf(fv, wA, oa[r]);
                    ob[r] = fmaf(fv, wB, ob[r]);
                }
            }
        }

        // bn3 + residual + relu
        #pragma unroll
        for (int r = 0; r < 4; r++) {
            int n = n0 + r;
            if (n < N) {
                float xa = x[(size_t)n * 64 + lane];
                float xc = x[(size_t)n * 64 + lane + 32];
                float va = fmaf(oa[r], s3a, k3a) + xa;
                float vb = fmaf(ob[r], s3b, k3b) + xc;
                out[(size_t)n * 64 + lane]      = fmaxf(va, 0.f);
                out[(size_t)n * 64 + lane + 32] = fmaxf(vb, 0.f);
            }
        }
        __syncwarp();
    }
}

extern "C" void kernel_launch(void* const* d_in, const int* in_sizes, int n_in,
                              void* d_out, int out_size)
{
    const float* p      = (const float*)d_in[0];
    const float* x      = (const float*)d_in[1];
    const int*   idx    = (const int*)  d_in[2];
    const float* w1     = (const float*)d_in[3];
    const float* g1     = (const float*)d_in[4];
    const float* b1     = (const float*)d_in[5];
    const float* m1     = (const float*)d_in[6];
    const float* v1     = (const float*)d_in[7];
    const float* conv_w = (const float*)d_in[8];
    const float* g2     = (const float*)d_in[9];
    const float* b2     = (const float*)d_in[10];
    const float* m2     = (const float*)d_in[11];
    const float* v2     = (const float*)d_in[12];
    const float* w3     = (const float*)d_in[13];
    const float* g3     = (const float*)d_in[14];
    const float* b3     = (const float*)d_in[15];
    const float* m3     = (const float*)d_in[16];
    const float* v3     = (const float*)d_in[17];
    float* out = (float*)d_out;

    int N = in_sizes[0] / 3;
    if (N > NMAX) N = NMAX;

    edge_kernel_a<<<1184, 256>>>(p, x, w1, g1, b1, m1, v1, conv_w, N);
    edge_kernel_b<<<1184, 256>>>(p, x, idx, conv_w,
                                 g2, b2, m2, v2,
                                 w3, g3, b3, m3, v3,
                                 out, N);
}

// round 9
// speedup vs baseline: 1.9863x; 1.0714x over previous
#include <cuda_runtime.h>

#define NMAX 100000
#define EPSV 1e-5f

// Scratch: hq[n][o] = hw[n][o] + p[n]·conv_w[o,0:3],
//   hw[n][o] = sum_h relu(bn1(x@w1))[n][h] * conv_w[o][3+h]
__device__ __align__(256) float g_hq[NMAX * 64];

// ---- packed f32x2 helpers (sm_103a FFMA2 path) ----
typedef unsigned long long ull;
__device__ __forceinline__ ull pk2(float lo, float hi) {
    ull r; asm("mov.b64 %0, {%1, %2};" : "=l"(r) : "f"(lo), "f"(hi)); return r;
}
__device__ __forceinline__ void unpk2(ull v, float& lo, float& hi) {
    asm("mov.b64 {%0, %1}, %2;" : "=f"(lo), "=f"(hi) : "l"(v));
}
__device__ __forceinline__ ull ffma2(ull a, ull b, ull c) {
    ull d; asm("fma.rn.f32x2 %0, %1, %2, %3;" : "=l"(d) : "l"(a), "l"(b), "l"(c)); return d;
}

// ---------------------------------------------------------------------------
// Kernel A: 4 rows/warp. Lane owns OUTPUT channels (2l, 2l+1).
// GEMVs packed along the reduction dim: acc lo-half = even-c partial sum,
// hi-half = odd-c partial sum; one lo+hi add in the epilogue.
// Weight smem tile w[c2*64+o] = float2{w[2c2][o], w[2c2+1][o]}; lane fetches
// both its outputs' c-pair weights with a single LDS.128.
// ---------------------------------------------------------------------------
__global__ __launch_bounds__(256) void edge_kernel_a(
    const float* __restrict__ p,
    const float* __restrict__ x,
    const float* __restrict__ w1,
    const float* __restrict__ g1, const float* __restrict__ b1,
    const float* __restrict__ m1, const float* __restrict__ v1,
    const float* __restrict__ conv_w,
    int N)
{
    __shared__ __align__(16) float2 w1p[32 * 64];   // (c2, o): {w1[2c2][o], w1[2c2+1][o]}
    __shared__ __align__(16) float2 w2p[32 * 64];   // (h2, o): {cw[o][3+2h2], cw[o][3+2h2+1]}
    __shared__ float s1sm[64], c1sm[64];
    __shared__ __align__(16) float xbuf[8][4][64];

    const int tid = threadIdx.x;
    for (int i = tid; i < 32 * 64; i += 256) {
        int c2 = i >> 6, o = i & 63;
        w1p[i] = make_float2(w1[(2 * c2) * 64 + o], w1[(2 * c2 + 1) * 64 + o]);
        w2p[i] = make_float2(conv_w[o * 67 + 3 + 2 * c2], conv_w[o * 67 + 3 + 2 * c2 + 1]);
    }
    if (tid < 64) {
        float s = g1[tid] * rsqrtf(v1[tid] + EPSV);
        s1sm[tid] = s;
        c1sm[tid] = b1[tid] - m1[tid] * s;
    }
    __syncthreads();

    const int lane = tid & 31;
    const int wrp  = tid >> 5;
    const int oA = 2 * lane, oB = 2 * lane + 1;

    const float wxa = conv_w[oA * 67 + 0], wya = conv_w[oA * 67 + 1], wza = conv_w[oA * 67 + 2];
    const float wxb = conv_w[oB * 67 + 0], wyb = conv_w[oB * 67 + 1], wzb = conv_w[oB * 67 + 2];
    const float s1a = s1sm[oA], c1a = c1sm[oA];
    const float s1b = s1sm[oB], c1b = c1sm[oB];

    const int group   = blockIdx.x * 8 + wrp;
    const int nGroups = gridDim.x * 8;
    float (*X)[64] = xbuf[wrp];

    for (int n0 = group * 4; n0 < N; n0 += nGroups * 4) {
        int   nr[4];
        float px[4], py[4], pz[4];
        #pragma unroll
        for (int r = 0; r < 4; r++) {
            int n = n0 + r; if (n >= N) n = N - 1;
            nr[r] = n;
            float2 xv = reinterpret_cast<const float2*>(x + (size_t)n * 64)[lane];
            *reinterpret_cast<float2*>(&X[r][2 * lane]) = xv;
            px[r] = p[n * 3 + 0]; py[r] = p[n * 3 + 1]; pz[r] = p[n * 3 + 2];
        }
        __syncwarp();

        // ---- GEMV 1: h = x @ w1 (packed along c) ----
        ull accA[4], accB[4];
        #pragma unroll
        for (int r = 0; r < 4; r++) { accA[r] = 0ull; accB[r] = 0ull; }
        #pragma unroll
        for (int c4 = 0; c4 < 64; c4 += 4) {
            const int c2 = c4 >> 1;
            ulonglong2 wv0 = *reinterpret_cast<const ulonglong2*>(&w1p[c2 * 64 + oA]);
            ulonglong2 wv1 = *reinterpret_cast<const ulonglong2*>(&w1p[(c2 + 1) * 64 + oA]);
            #pragma unroll
            for (int r = 0; r < 4; r++) {
                ulonglong2 xv = *reinterpret_cast<const ulonglong2*>(&X[r][c4]);
                accA[r] = ffma2(xv.x, wv0.x, accA[r]);
                accB[r] = ffma2(xv.x, wv0.y, accB[r]);
                accA[r] = ffma2(xv.y, wv1.x, accA[r]);
                accB[r] = ffma2(xv.y, wv1.y, accB[r]);
            }
        }
        __syncwarp();
        #pragma unroll
        for (int r = 0; r < 4; r++) {
            float alo, ahi, blo, bhi;
            unpk2(accA[r], alo, ahi);
            unpk2(accB[r], blo, bhi);
            float hA = fmaxf(fmaf(alo + ahi, s1a, c1a), 0.f);
            float hB = fmaxf(fmaf(blo + bhi, s1b, c1b), 0.f);
            *reinterpret_cast<float2*>(&X[r][2 * lane]) = make_float2(hA, hB);
        }
        __syncwarp();

        // ---- GEMV 2: hw = h @ conv_w[:,3:]^T ----
        #pragma unroll
        for (int r = 0; r < 4; r++) { accA[r] = 0ull; accB[r] = 0ull; }
        #pragma unroll
        for (int c4 = 0; c4 < 64; c4 += 4) {
            const int c2 = c4 >> 1;
            ulonglong2 wv0 = *reinterpret_cast<const ulonglong2*>(&w2p[c2 * 64 + oA]);
            ulonglong2 wv1 = *reinterpret_cast<const ulonglong2*>(&w2p[(c2 + 1) * 64 + oA]);
            #pragma unroll
            for (int r = 0; r < 4; r++) {
                ulonglong2 hv = *reinterpret_cast<const ulonglong2*>(&X[r][c4]);
                accA[r] = ffma2(hv.x, wv0.x, accA[r]);
                accB[r] = ffma2(hv.x, wv0.y, accB[r]);
                accA[r] = ffma2(hv.y, wv1.x, accA[r]);
                accB[r] = ffma2(hv.y, wv1.y, accB[r]);
            }
        }

        #pragma unroll
        for (int r = 0; r < 4; r++) {
            if (n0 + r < N) {
                float alo, ahi, blo, bhi;
                unpk2(accA[r], alo, ahi);
                unpk2(accB[r], blo, bhi);
                float qa = fmaf(px[r], wxa, fmaf(py[r], wya, fmaf(pz[r], wza, alo + ahi)));
                float qb = fmaf(px[r], wxb, fmaf(py[r], wyb, fmaf(pz[r], wzb, blo + bhi)));
                *reinterpret_cast<float2*>(g_hq + (size_t)nr[r] * 64 + 2 * lane) =
                    make_float2(qa, qb);
            }
        }
        __syncwarp();   // buffer reuse next iteration
    }
}

// ---------------------------------------------------------------------------
// Kernel B: 4 points/warp. Lane owns channels (2l, 2l+1) in BOTH phases.
// Gather: one LDG.64/lane/k, bn2 via one FFMA2, relu folded into max (init 0).
// GEMV: packed along c, weights via one LDS.128 per (c2, lane).
// ---------------------------------------------------------------------------
__global__ __launch_bounds__(256) void edge_kernel_b(
    const float* __restrict__ p, const float* __restrict__ x,
    const int*   __restrict__ idx,
    const float* __restrict__ conv_w,
    const float* __restrict__ g2, const float* __restrict__ b2,
    const float* __restrict__ m2, const float* __restrict__ v2,
    const float* __restrict__ w3,
    const float* __restrict__ g3, const float* __restrict__ b3,
    const float* __restrict__ m3, const float* __restrict__ v3,
    float* __restrict__ out, int N)
{
    __shared__ __align__(16) float2 w3p[32 * 64];   // (c2, o): {w3[2c2][o], w3[2c2+1][o]}
    __shared__ __align__(16) float fbuf[8][4][64];

    const int tid = threadIdx.x;
    for (int i = tid; i < 32 * 64; i += 256) {
        int c2 = i >> 6, o = i & 63;
        w3p[i] = make_float2(w3[(2 * c2) * 64 + o], w3[(2 * c2 + 1) * 64 + o]);
    }

    const int lane = tid & 31;
    const int wrp  = tid >> 5;
    const int oA = 2 * lane, oB = 2 * lane + 1;

    const float s2a = g2[oA] * rsqrtf(v2[oA] + EPSV);
    const float k2a = b2[oA] - m2[oA] * s2a;
    const float s2b = g2[oB] * rsqrtf(v2[oB] + EPSV);
    const float k2b = b2[oB] - m2[oB] * s2b;
    const float wax = conv_w[oA * 67 + 0], way = conv_w[oA * 67 + 1], waz = conv_w[oA * 67 + 2];
    const float wbx = conv_w[oB * 67 + 0], wby = conv_w[oB * 67 + 1], wbz = conv_w[oB * 67 + 2];
    const ull s2p = pk2(s2a, s2b);
    const float s3a = g3[oA] * rsqrtf(v3[oA] + EPSV);
    const float k3a = b3[oA] - m3[oA] * s3a;
    const float s3b = g3[oB] * rsqrtf(v3[oB] + EPSV);
    const float k3b = b3[oB] - m3[oB] * s3b;
    __syncthreads();

    const int group   = blockIdx.x * 8 + wrp;
    const int nGroups = gridDim.x * 8;
    float (*F)[64] = fbuf[wrp];
    const long long maxIdxAddr = (long long)N * 16 - 1;

    for (int n0 = group * 4; n0 < N; n0 += nGroups * 4) {
        // 64 neighbor indices (4 rows x 16) via 2 coalesced loads
        long long base = (long long)n0 * 16;
        long long a0 = base + lane;        if (a0 > maxIdxAddr) a0 = maxIdxAddr;
        long long a1 = base + 32 + lane;   if (a1 > maxIdxAddr) a1 = maxIdxAddr;
        int j0 = idx[a0];
        int j1 = idx[a1];

        // per-row folded bias pack: {k2 - (p[n]·w)·s2} for channels oA,oB
        ull cp[4];
        #pragma unroll
        for (int r = 0; r < 4; r++) {
            int n = n0 + r; if (n >= N) n = N - 1;
            float px = p[n * 3 + 0], py = p[n * 3 + 1], pz = p[n * 3 + 2];
            float pwa = fmaf(px, wax, fmaf(py, way, pz * waz));
            float pwb = fmaf(px, wbx, fmaf(py, wby, pz * wbz));
            cp[r] = pk2(fmaf(-pwa, s2a, k2a), fmaf(-pwb, s2b, k2b));
        }

        // gather + bn2 + relu-folded max
        float ma[4] = {0.f, 0.f, 0.f, 0.f};
        float mb[4] = {0.f, 0.f, 0.f, 0.f};
        #pragma unroll
        for (int r = 0; r < 4; r++) {
            #pragma unroll
            for (int k = 0; k < 16; k++) {
                const int e = r * 16 + k;
                int j = __shfl_sync(0xffffffffu, (e < 32) ? j0 : j1, e & 31);
                ull hq2 = *reinterpret_cast<const ull*>(g_hq + (size_t)j * 64 + oA);
                ull ev = ffma2(hq2, s2p, cp[r]);
                float e0, e1;
                unpk2(ev, e0, e1);
                ma[r] = fmaxf(ma[r], e0);
                mb[r] = fmaxf(mb[r], e1);
            }
        }

        __syncwarp();
        #pragma unroll
        for (int r = 0; r < 4; r++)
            *reinterpret_cast<float2*>(&F[r][oA]) = make_float2(ma[r], mb[r]);
        __syncwarp();

        // ---- GEMV: out = f @ w3 (packed along c) ----
        ull accA[4], accB[4];
        #pragma unroll
        for (int r = 0; r < 4; r++) { accA[r] = 0ull; accB[r] = 0ull; }
        #pragma unroll
        for (int c4 = 0; c4 < 64; c4 += 4) {
            const int c2 = c4 >> 1;
            ulonglong2 wv0 = *reinterpret_cast<const ulonglong2*>(&w3p[c2 * 64 + oA]);
            ulonglong2 wv1 = *reinterpret_cast<const ulonglong2*>(&w3p[(c2 + 1) * 64 + oA]);
            #pragma unroll
            for (int r = 0; r < 4; r++) {
                ulonglong2 fv = *reinterpret_cast<const ulonglong2*>(&F[r][c4]);
                accA[r] = ffma2(fv.x, wv0.x, accA[r]);
                accB[r] = ffma2(fv.x, wv0.y, accB[r]);
                accA[r] = ffma2(fv.y, wv1.x, accA[r]);
                accB[r] = ffma2(fv.y, wv1.y, accB[r]);
            }
        }

        // bn3 + residual + relu
        #pragma unroll
        for (int r = 0; r < 4; r++) {
            int n = n0 + r;
            if (n < N) {
                float alo, ahi, blo, bhi;
                unpk2(accA[r], alo, ahi);
                unpk2(accB[r], blo, bhi);
                float2 xr = *reinterpret_cast<const float2*>(x + (size_t)n * 64 + oA);
                float va = fmaf(alo + ahi, s3a, k3a) + xr.x;
                float vb = fmaf(blo + bhi, s3b, k3b) + xr.y;
                *reinterpret_cast<float2*>(out + (size_t)n * 64 + oA) =
                    make_float2(fmaxf(va, 0.f), fmaxf(vb, 0.f));
            }
        }
        __syncwarp();
    }
}

extern "C" void kernel_launch(void* const* d_in, const int* in_sizes, int n_in,
                              void* d_out, int out_size)
{
    const float* p      = (const float*)d_in[0];
    const float* x      = (const float*)d_in[1];
    const int*   idx    = (const int*)  d_in[2];
    const float* w1     = (const float*)d_in[3];
    const float* g1     = (const float*)d_in[4];
    const float* b1     = (const float*)d_in[5];
    const float* m1     = (const float*)d_in[6];
    const float* v1     = (const float*)d_in[7];
    const float* conv_w = (const float*)d_in[8];
    const float* g2     = (const float*)d_in[9];
    const float* b2     = (const float*)d_in[10];
    const float* m2     = (const float*)d_in[11];
    const float* v2     = (const float*)d_in[12];
    const float* w3     = (const float*)d_in[13];
    const float* g3     = (const float*)d_in[14];
    const float* b3     = (const float*)d_in[15];
    const float* m3     = (const float*)d_in[16];
    const float* v3     = (const float*)d_in[17];
    float* out = (float*)d_out;

    int N = in_sizes[0] / 3;
    if (N > NMAX) N = NMAX;

    edge_kernel_a<<<1184, 256>>>(p, x, w1, g1, b1, m1, v1, conv_w, N);
    edge_kernel_b<<<1184, 256>>>(p, x, idx, conv_w,
                                 g2, b2, m2, v2,
                                 w3, g3, b3, m3, v3,
                                 out, N);
}